// round 10
// baseline (speedup 1.0000x reference)
#include <cuda_runtime.h>
#include <cuda_bf16.h>
#include <cstddef>

// Problem constants (from reference)
#define NFRAMES 8
#define NLOC    4096
#define NALL    8192
#define NNEI    256
#define NTYPES  4
#define NSPLINE 1024

static constexpr int THREADS        = 1024; // 32 warps/CTA
static constexpr int WARPS          = THREADS / 32;
static constexpr int CHUNKS         = 4;    // chunks per (frame, type) bin
static constexpr int CTAS_X         = NTYPES * CHUNKS; // 16 -> grid (16, 8) = 128 CTAs

// Scratch for type binning (device globals: allocation-free)
__device__ int g_counts[NFRAMES * NTYPES];
__device__ int g_lists [NFRAMES * NTYPES * NLOC];

// ---------------- Pre-pass: bin local atoms by their own type ----------------
__global__ __launch_bounds__(THREADS, 1)
void bin_by_type_kernel(const int* __restrict__ atype) // (NFRAMES, NALL)
{
    const int f   = blockIdx.x;
    const int tid = threadIdx.x;
    __shared__ int s_hist[NTYPES];
    __shared__ int s_off [NTYPES];

    if (tid < NTYPES) { s_hist[tid] = 0; }
    __syncthreads();

    const int* af = atype + (size_t)f * NALL; // local atoms are the first NLOC
    for (int a = tid; a < NLOC; a += THREADS)
        atomicAdd(&s_hist[af[a]], 1);
    __syncthreads();

    if (tid < NTYPES) {
        g_counts[f * NTYPES + tid] = s_hist[tid];
        s_off[tid] = 0;
    }
    __syncthreads();

    for (int a = tid; a < NLOC; a += THREADS) {
        const int t    = af[a];
        const int slot = atomicAdd(&s_off[t], 1);
        g_lists[(f * NTYPES + t) * NLOC + slot] = a;
    }
}

// ---------------- Main kernel ----------------
// Dynamic smem: s_pack float4[NALL] (128KB) + s_tab float4[NTYPES*NSPLINE] (64KB)
__global__ __launch_bounds__(THREADS, 1)
void pairtab_energy_kernel(const float*  __restrict__ coord,   // (NFRAMES, NALL, 3)
                           const int*    __restrict__ atype,   // (NFRAMES, NALL)
                           const int*    __restrict__ nlist,   // (NFRAMES, NLOC, NNEI)
                           const float4* __restrict__ tab,     // (NTYPES,NTYPES,NSPLINE) float4
                           float*        __restrict__ out)     // (NFRAMES, NLOC)
{
    extern __shared__ float4 s_mem[];
    float4* s_pack = s_mem;          // [NALL]
    float4* s_tab  = s_mem + NALL;   // [NTYPES * NSPLINE]

    const int f     = blockIdx.y;
    const int t     = blockIdx.x >> 2;   // i_type this CTA serves
    const int chunk = blockIdx.x & 3;
    const int tid   = threadIdx.x;

    // ---- Stage coords + types of this frame (coalesced) ----
    {
        const float* cf = coord + (size_t)f * NALL * 3;
        const int*   af = atype + (size_t)f * NALL;
        for (int a = tid; a < NALL; a += THREADS) {
            float x = cf[a * 3 + 0];
            float y = cf[a * 3 + 1];
            float z = cf[a * 3 + 2];
            int   ty = af[a];
            s_pack[a] = make_float4(x, y, z, __int_as_float(ty));
        }
    }
    // ---- Stage tab[t] : NTYPES*NSPLINE float4 = 64KB (coalesced) ----
    {
        const float4* tf = tab + (size_t)t * NTYPES * NSPLINE;
        for (int i = tid; i < NTYPES * NSPLINE; i += THREADS)
            s_tab[i] = tf[i];
    }
    __syncthreads();

    const int lane = tid & 31;
    const int wid  = tid >> 5;

    const int  cnt   = g_counts[f * NTYPES + t];
    const int  m     = (cnt + CHUNKS - 1) / CHUNKS;
    const int  start = chunk * m;
    const int  end   = min(start + m, cnt);
    const int* list  = g_lists + (f * NTYPES + t) * NLOC;

    for (int k = start + wid; k < end; k += WARPS) {
        const int atom = list[k];
        const float4 pi = s_pack[atom];

        const int4* nl = reinterpret_cast<const int4*>(
            nlist + ((size_t)f * NLOC + atom) * NNEI);

        // ---- Stage 0: both nlist quads up front ----
        const int4 n0 = nl[lane];
        const int4 n1 = nl[32 + lane];
        const int js[8] = { n0.x, n0.y, n0.z, n0.w, n1.x, n1.y, n1.z, n1.w };

        // ---- Stage 1: 8 coord gathers, front-batched ----
        float4 pj[8];
        #pragma unroll
        for (int i = 0; i < 8; ++i)
            pj[i] = s_pack[js[i] >= 0 ? js[i] : 0];

        // ---- Stage 2: collapse each pj to (uu, table base) ----
        float uu[8];
        int   tb[8];
        #pragma unroll
        for (int i = 0; i < 8; ++i) {
            const float dx = __fadd_rn(pi.x, -pj[i].x);
            const float dy = __fadd_rn(pi.y, -pj[i].y);
            const float dz = __fadd_rn(pi.z, -pj[i].z);
            // Reference association (verified R5): (dx^2 + dz^2) + dy^2,
            // fully uncontracted, then * 50.0f (XLA's reciprocal of 0.02f).
            const float sxz = __fadd_rn(__fmul_rn(dx, dx), __fmul_rn(dz, dz));
            const float r2  = __fadd_rn(sxz, __fmul_rn(dy, dy));
            const float rr  = __fsqrt_rn(r2);
            float u = __fmul_rn(rr, 50.0f);
            if (js[i] < 0) u = 1.0e9f;           // invalid -> out of table range
            uu[i] = u;
            tb[i] = __float_as_int(pj[i].w) * NSPLINE;
        }

        // ---- Stage 3: 8 table gathers, front-batched ----
        float4 cc[8];
        #pragma unroll
        for (int i = 0; i < 8; ++i) {
            const int idx = (int)uu[i];
            cc[i] = s_tab[tb[i] + min(idx, NSPLINE - 1)];
        }

        // ---- Stage 4: Horner + dual accumulators ----
        float acc0 = 0.0f, acc1 = 0.0f;
        #pragma unroll
        for (int i = 0; i < 8; ++i) {
            const int   idx  = (int)uu[i];
            const float frac = __fadd_rn(uu[i], -(float)idx);
            float e = fmaf(cc[i].w, frac, cc[i].z);
            e = fmaf(e, frac, cc[i].y);
            e = fmaf(e, frac, cc[i].x);
            e = (idx < NSPLINE) ? e : 0.0f;
            if (i & 1) acc1 += e; else acc0 += e;
        }
        float acc = acc0 + acc1;

        // Warp reduction
        #pragma unroll
        for (int o = 16; o > 0; o >>= 1)
            acc += __shfl_xor_sync(0xffffffffu, acc, o);

        if (lane == 0)
            out[(size_t)f * NLOC + atom] = 0.5f * acc;
    }
}

extern "C" void kernel_launch(void* const* d_in, const int* in_sizes, int n_in,
                              void* d_out, int out_size)
{
    const float*  coord = (const float*)  d_in[0]; // (8, 8192, 3) f32
    const int*    atype = (const int*)    d_in[1]; // (8, 8192) i32
    const int*    nlist = (const int*)    d_in[2]; // (8, 4096, 256) i32
    const float4* tab   = (const float4*) d_in[3]; // (4, 4, 1024, 4) f32 -> float4
    float*        out   = (float*)        d_out;   // (8, 4096) f32

    const int smem_bytes = (NALL + NTYPES * NSPLINE) * (int)sizeof(float4); // 196608
    static bool attr_set = false;
    if (!attr_set) {
        cudaFuncSetAttribute(pairtab_energy_kernel,
                             cudaFuncAttributeMaxDynamicSharedMemorySize, smem_bytes);
        attr_set = true;
    }

    bin_by_type_kernel<<<NFRAMES, THREADS>>>(atype);

    dim3 grid(CTAS_X, NFRAMES);
    pairtab_energy_kernel<<<grid, THREADS, smem_bytes>>>(coord, atype, nlist, tab, out);
}